// round 12
// baseline (speedup 1.0000x reference)
#include <cuda_runtime.h>
#include <cuda_fp16.h>

#define N_MAX 100000
#define E_MAX 1700000

// ---------------- static device scratch ----------------
__device__ __align__(16) __half g_t[(size_t)N_MAX * 64];  // GEMM out / prop in (fp16)
__device__ __align__(16) float  g_h[(size_t)N_MAX * 64];  // prop out / GEMM in (fp32)
__device__ __align__(16) int2   g_meta[E_MAX];  // CSR: (src, w-bits) per edge (by dst)
__device__ int   g_deg[N_MAX];               // RAW in-degree; zero-init, k_reset'd
__device__ int   g_cur[N_MAX];               // scatter cursors; zero-init, k_reset'd
__device__ int   g_off[N_MAX + 1];           // CSR offsets, block-LOCAL (add g_bsums)
__device__ float g_dinv[N_MAX];              // (deg+1)^-1/2
__device__ int   g_bsums[256];               // scan block sums (exclusive after scan1f)
__device__ int   g_done;                     // scan1f completion counter (self-reset)

__device__ __forceinline__ int foff(int i) {   // final CSR offset
    return g_off[i] + g_bsums[i >> 10];
}

// ---------------- side stream for fork-join overlap (created pre-baseline) ---
static cudaStream_t g_s2;
static cudaEvent_t  g_evA, g_evB, g_evC;
static struct SideInit {
    SideInit() {
        cudaStreamCreateWithFlags(&g_s2, cudaStreamNonBlocking);
        cudaEventCreateWithFlags(&g_evA, cudaEventDisableTiming);
        cudaEventCreateWithFlags(&g_evB, cudaEventDisableTiming);
        cudaEventCreateWithFlags(&g_evC, cudaEventDisableTiming);
    }
} g_side_init;

// ---------------- graph preprocessing ----------------
// edge_index is int32 (JAX x64 disabled downcasts jnp.int64 -> int32)
__global__ void k_count(const int* __restrict__ ei, int E) {
    int e = blockIdx.x * blockDim.x + threadIdx.x;
    if (e < E) atomicAdd(&g_deg[ei[E + e]], 1);
}

// scan of raw deg over 1024-elem tiles + fused dinv; LAST finishing block also
// performs the cross-block scan of g_bsums.
__global__ __launch_bounds__(256) void k_scan1f(int n, int nb) {
    __shared__ int wsum[8];
    __shared__ int sh[256];
    __shared__ int isLast;
    int tid = threadIdx.x;
    int base = blockIdx.x * 1024 + tid * 4;
    int v[4];
#pragma unroll
    for (int j = 0; j < 4; j++) {
        int i = base + j;
        int draw = (i < n) ? g_deg[i] : 0;
        v[j] = draw;
        if (i < n) g_dinv[i] = rsqrtf((float)(draw + 1));
    }
    int s = v[0] + v[1] + v[2] + v[3];
    int lane = tid & 31, w = tid >> 5;
    int ps = s;
#pragma unroll
    for (int o = 1; o < 32; o <<= 1) {
        int t = __shfl_up_sync(0xffffffffu, ps, o);
        if (lane >= o) ps += t;
    }
    if (lane == 31) wsum[w] = ps;
    __syncthreads();
    if (w == 0) {
        int t = (lane < 8) ? wsum[lane] : 0;
#pragma unroll
        for (int o = 1; o < 8; o <<= 1) {
            int u = __shfl_up_sync(0xffffffffu, t, o);
            if (lane >= o) t += u;
        }
        if (lane < 8) wsum[lane] = t;
    }
    __syncthreads();
    int run = ps - s + (w ? wsum[w - 1] : 0);
#pragma unroll
    for (int j = 0; j < 4; j++) {
        int i = base + j;
        if (i < n) g_off[i] = run;
        else if (i == n) g_off[n] = run;
        run += v[j];
    }
    if (tid == 0) g_bsums[blockIdx.x] = wsum[7];

    __threadfence();
    if (tid == 0) {
        int old = atomicAdd(&g_done, 1);
        isLast = (old == nb - 1);
    }
    __syncthreads();
    if (isLast) {
        int val = (tid < nb) ? ((volatile int*)g_bsums)[tid] : 0;
        sh[tid] = val;
        __syncthreads();
        for (int o = 1; o < 256; o <<= 1) {
            int t = (tid >= o) ? sh[tid - o] : 0;
            __syncthreads();
            sh[tid] += t;
            __syncthreads();
        }
        g_bsums[tid] = sh[tid] - val;
        if (tid == 0) g_done = 0;
    }
}

__global__ void k_scatter(const int* __restrict__ ei, int E) {
    int e = blockIdx.x * blockDim.x + threadIdx.x;
    if (e >= E) return;
    int s = ei[e];
    int d = ei[E + e];
    int pos = foff(d) + atomicAdd(&g_cur[d], 1);
    g_meta[pos] = make_int2(s, __float_as_int(g_dinv[s] * g_dinv[d]));
}

__global__ void k_reset(int n) {
    int i = blockIdx.x * blockDim.x + threadIdx.x;
    if (i < n) { g_deg[i] = 0; g_cur[i] = 0; }
}

// ---------------- packed f32x2 helpers ----------------
__device__ __forceinline__ void ffma2(unsigned long long& d,
                                      unsigned long long a, unsigned long long b) {
    asm("fma.rn.f32x2 %0, %1, %2, %0;" : "+l"(d) : "l"(a), "l"(b));
}
__device__ __forceinline__ float2 unpk(unsigned long long v) {
    float2 r;
    asm("mov.b64 {%0, %1}, %2;" : "=f"(r.x), "=f"(r.y) : "l"(v));
    return r;
}

// ---------------- GEMM: g_t[n,64](fp16) = A[n,K](fp32) @ W[K,64] -------------
// A == nullptr -> read g_h. 128x64 tile, 256 thr, 4 blocks/SM. Accumulators
// pair ADJACENT ROWS (direct LDS.64 a-operand). W tile is stored PRE-DUPLICATED
// ({w,w} pairs) so the inner loop is 4 LDS.64 + 2 LDS.128 + 16 FFMA2 — no MOVs.
template <int K>
__global__ __launch_bounds__(256, 4) void k_gemm(const float* __restrict__ Ain,
                                                 const float* __restrict__ W, int n) {
    const float* A = Ain ? Ain : g_h;
    constexpr int KC = 32;
    constexpr int PF = 2 * KC + 4;                   // 68 floats per pair-row
    __shared__ __align__(16) float Xs[64 * PF];      // 17408 B
    __shared__ __align__(16) float Wsh2[KC * 128];   // 16384 B (pre-duplicated)

    int tid = threadIdx.x;
    int row0 = blockIdx.x * 128;
    int tx = tid & 15, ty = tid >> 4;
    int c0 = tx * 4;
    int p0 = ty * 4;                                 // first row-pair

    unsigned long long acc[4][4];                    // [row-pair][col]
#pragma unroll
    for (int i = 0; i < 4; i++)
#pragma unroll
        for (int j = 0; j < 4; j++) acc[i][j] = 0ull;

    for (int kc = 0; kc < K; kc += KC) {
        __syncthreads();
        // X chunk: coalesced float4 loads, pair-interleaved scalar stores
#pragma unroll
        for (int it = 0; it < 4; ++it) {
            int i = tid + it * 256;          // 1024 float4 slots
            int row = i >> 3;
            int k4 = (i & 7) * 4;
            int gr = row0 + row;
            float4 v = make_float4(0.f, 0.f, 0.f, 0.f);
            if (gr < n) v = *(const float4*)&A[(size_t)gr * K + kc + k4];
            int base = (row >> 1) * PF + (row & 1);
            Xs[base + 2 * (k4 + 0)] = v.x;
            Xs[base + 2 * (k4 + 1)] = v.y;
            Xs[base + 2 * (k4 + 2)] = v.z;
            Xs[base + 2 * (k4 + 3)] = v.w;
        }
        // W chunk: load float4, store duplicated {x,x,y,y} {z,z,w,w}
#pragma unroll
        for (int it = 0; it < 2; ++it) {
            int i = tid + it * 256;          // 512 float4 slots (32k x 16c4)
            int k = i >> 4;
            int c4 = (i & 15) * 4;
            float4 v = *(const float4*)&W[(size_t)kc * 64 + i * 4];
            int base = k * 128 + c4 * 2;
            *(float4*)&Wsh2[base]     = make_float4(v.x, v.x, v.y, v.y);
            *(float4*)&Wsh2[base + 4] = make_float4(v.z, v.z, v.w, v.w);
        }
        __syncthreads();

#pragma unroll
        for (int k = 0; k < KC; ++k) {
            ulonglong2 wa = *(const ulonglong2*)&Wsh2[k * 128 + c0 * 2];     // w0,w1
            ulonglong2 wb = *(const ulonglong2*)&Wsh2[k * 128 + c0 * 2 + 4]; // w2,w3
#pragma unroll
            for (int i = 0; i < 4; i++) {
                unsigned long long x2 =
                    *(const unsigned long long*)&Xs[(p0 + i) * PF + 2 * k];
                ffma2(acc[i][0], x2, wa.x);
                ffma2(acc[i][1], x2, wa.y);
                ffma2(acc[i][2], x2, wb.x);
                ffma2(acc[i][3], x2, wb.y);
            }
        }
    }

#pragma unroll
    for (int i = 0; i < 4; i++) {
        int gr = row0 + (p0 + i) * 2;
        float2 a0 = unpk(acc[i][0]), a1 = unpk(acc[i][1]);
        float2 a2 = unpk(acc[i][2]), a3 = unpk(acc[i][3]);
        if (gr < n) {
            __half2 h01 = __floats2half2_rn(a0.x, a1.x);
            __half2 h23 = __floats2half2_rn(a2.x, a3.x);
            *(uint2*)&g_t[(size_t)gr * 64 + c0] =
                make_uint2(*(unsigned*)&h01, *(unsigned*)&h23);
        }
        if (gr + 1 < n) {
            __half2 h01 = __floats2half2_rn(a0.y, a1.y);
            __half2 h23 = __floats2half2_rn(a2.y, a3.y);
            *(uint2*)&g_t[(size_t)(gr + 1) * 64 + c0] =
                make_uint2(*(unsigned*)&h01, *(unsigned*)&h23);
        }
    }
}

// ---------------- propagation: out[d] = sum_{e: dst=d} w_e * t[src_e]
//                   + dinv[d]^2 * t[d] (+bias) (+relu), t in fp16 -------------
// Warp per node, lane owns one half2 (2 feats). Batch-8 gather (MLP=8),
// dual fp32 accumulator streams. No atomics.
__global__ __launch_bounds__(256) void k_prop(float* __restrict__ outp,
                                              const float* __restrict__ bias, int relu,
                                              int n) {
    float* out = outp ? outp : g_h;
    const __half2* t2 = (const __half2*)g_t;     // row = 32 half2
    int node = (blockIdx.x * blockDim.x + threadIdx.x) >> 5;
    int lane = threadIdx.x & 31;
    if (node >= n) return;
    int beg = foff(node), end = foff(node + 1);
    const __half2* tf = t2 + lane;

    float ax0 = 0.f, ay0 = 0.f, ax1 = 0.f, ay1 = 0.f;
    for (int j = beg; j < end; j += 32) {
        int m = end - j;
        if (m > 32) m = 32;
        int sv = 0;
        float wv = 0.f;
        if (lane < m) {
            int2 mw = g_meta[j + lane];
            sv = mw.x;
            wv = __int_as_float(mw.y);
        }
        int nb8 = (m + 7) >> 3;
        for (int b = 0; b < nb8; ++b) {
            int bb = b * 8;
            int s[8];
            float w[8];
            __half2 v[8];
#pragma unroll
            for (int i = 0; i < 8; i++) {
                s[i] = __shfl_sync(0xffffffffu, sv, bb + i);
                w[i] = __shfl_sync(0xffffffffu, wv, bb + i);
            }
#pragma unroll
            for (int i = 0; i < 8; i++) v[i] = tf[(size_t)s[i] * 32];
#pragma unroll
            for (int i = 0; i < 8; i++) {
                float2 f = __half22float2(v[i]);
                if (i & 1) { ax1 = fmaf(w[i], f.x, ax1); ay1 = fmaf(w[i], f.y, ay1); }
                else       { ax0 = fmaf(w[i], f.x, ax0); ay0 = fmaf(w[i], f.y, ay0); }
            }
        }
    }
    float accx = ax0 + ax1, accy = ay0 + ay1;
    // self loop
    float dv = g_dinv[node];
    float2 v0 = __half22float2(tf[(size_t)node * 32]);
    float w0 = dv * dv;
    accx = fmaf(w0, v0.x, accx);
    accy = fmaf(w0, v0.y, accy);
    if (bias) { accx += bias[2 * lane]; accy += bias[2 * lane + 1]; }
    if (relu) { accx = fmaxf(accx, 0.f); accy = fmaxf(accy, 0.f); }
    *(float2*)(out + (size_t)node * 64 + 2 * lane) = make_float2(accx, accy);
}

// ---------------- launch ----------------
extern "C" void kernel_launch(void* const* d_in, const int* in_sizes, int n_in,
                              void* d_out, int out_size) {
    const float* x     = (const float*)d_in[0];
    const int*   ei    = (const int*)d_in[1];     // int32 (JAX x64 disabled)
    const float* W_in  = (const float*)d_in[2];
    const float* b_in  = (const float*)d_in[3];
    const float* W_h   = (const float*)d_in[4];
    const float* b_h   = (const float*)d_in[5];
    const float* W_out = (const float*)d_in[6];

    int n = in_sizes[0] / 128;
    int E = in_sizes[1] / 2;

    int nb1 = (n + 1023) / 1024;
    int gb = (n + 127) / 128;
    int pb = (n + 7) / 8;

    // Fork: CSR build on side stream (init-free; k_reset of previous replay /
    // static zero-init provides zeroed g_deg/g_cur).
    cudaEventRecord(g_evA, 0);
    cudaStreamWaitEvent(g_s2, g_evA, 0);
    k_count  <<<(E + 255) / 256, 256, 0, g_s2>>>(ei, E);     // slot 1
    k_scan1f <<<nb1, 256, 0, g_s2>>>(n, nb1);                // slot 2
    k_scatter<<<(E + 255) / 256, 256, 0, g_s2>>>(ei, E);     // slot 3
    cudaEventRecord(g_evB, g_s2);

    // layer-1 GEMM overlaps CSR build — my-kernel slot 4 (ncu target)
    k_gemm<128><<<gb, 256>>>(x, W_in, n);

    // hidden reset tail on side stream (joined at the very end)
    k_reset<<<(n + 255) / 256, 256, 0, g_s2>>>(n);
    cudaEventRecord(g_evC, g_s2);

    // Join: prop needs both GEMM output and CSR
    cudaStreamWaitEvent(0, g_evB, 0);
    k_prop<<<pb, 256>>>(nullptr, b_in, 0, n);

    // hidden layers: h = relu(prop(h @ W_h[l]) + b_h[l])
    for (int l = 0; l < 3; ++l) {
        k_gemm<64><<<gb, 256>>>(nullptr, W_h + (size_t)l * 64 * 64, n);
        k_prop<<<pb, 256>>>(nullptr, b_h + (size_t)l * 64, 1, n);
    }

    // output layer: out = prop(h @ W_out), no bias, no relu
    k_gemm<64><<<gb, 256>>>(nullptr, W_out, n);
    k_prop<<<pb, 256>>>((float*)d_out, nullptr, 0, n);

    // join side stream (k_reset) so capture sees no unjoined work
    cudaStreamWaitEvent(0, g_evC, 0);
}

// round 13
// speedup vs baseline: 1.2273x; 1.2273x over previous
#include <cuda_runtime.h>
#include <cuda_fp16.h>

#define N_MAX 100000
#define E_MAX 1700000

// ---------------- static device scratch ----------------
__device__ __align__(16) __half g_t[(size_t)N_MAX * 64];  // GEMM out / prop in (fp16)
__device__ __align__(16) float  g_h[(size_t)N_MAX * 64];  // prop out / GEMM in (fp32)
__device__ __align__(16) int2   g_meta[E_MAX];  // CSR: (src, w-bits) per edge (by dst)
__device__ int   g_deg[N_MAX];               // RAW in-degree; zero-init, k_reset'd
__device__ int   g_cur[N_MAX];               // scatter cursors; zero-init, k_reset'd
__device__ int   g_off[N_MAX + 1];           // CSR offsets, block-LOCAL (add g_bsums)
__device__ float g_dinv[N_MAX];              // (deg+1)^-1/2
__device__ int   g_bsums[256];               // scan block sums (exclusive after scan1f)
__device__ int   g_done;                     // scan1f completion counter (self-reset)

__device__ __forceinline__ int foff(int i) {   // final CSR offset
    return g_off[i] + g_bsums[i >> 10];
}

// ---------------- side stream for fork-join overlap (created pre-baseline) ---
static cudaStream_t g_s2;
static cudaEvent_t  g_evA, g_evB, g_evC;
static struct SideInit {
    SideInit() {
        cudaStreamCreateWithFlags(&g_s2, cudaStreamNonBlocking);
        cudaEventCreateWithFlags(&g_evA, cudaEventDisableTiming);
        cudaEventCreateWithFlags(&g_evB, cudaEventDisableTiming);
        cudaEventCreateWithFlags(&g_evC, cudaEventDisableTiming);
    }
} g_side_init;

// ---------------- graph preprocessing ----------------
// edge_index is int32 (JAX x64 disabled downcasts jnp.int64 -> int32)
__global__ void k_count(const int* __restrict__ ei, int E) {
    int e = blockIdx.x * blockDim.x + threadIdx.x;
    if (e < E) atomicAdd(&g_deg[ei[E + e]], 1);
}

// scan of raw deg over 1024-elem tiles + fused dinv; LAST finishing block also
// performs the cross-block scan of g_bsums.
__global__ __launch_bounds__(256) void k_scan1f(int n, int nb) {
    __shared__ int wsum[8];
    __shared__ int sh[256];
    __shared__ int isLast;
    int tid = threadIdx.x;
    int base = blockIdx.x * 1024 + tid * 4;
    int v[4];
#pragma unroll
    for (int j = 0; j < 4; j++) {
        int i = base + j;
        int draw = (i < n) ? g_deg[i] : 0;
        v[j] = draw;
        if (i < n) g_dinv[i] = rsqrtf((float)(draw + 1));
    }
    int s = v[0] + v[1] + v[2] + v[3];
    int lane = tid & 31, w = tid >> 5;
    int ps = s;
#pragma unroll
    for (int o = 1; o < 32; o <<= 1) {
        int t = __shfl_up_sync(0xffffffffu, ps, o);
        if (lane >= o) ps += t;
    }
    if (lane == 31) wsum[w] = ps;
    __syncthreads();
    if (w == 0) {
        int t = (lane < 8) ? wsum[lane] : 0;
#pragma unroll
        for (int o = 1; o < 8; o <<= 1) {
            int u = __shfl_up_sync(0xffffffffu, t, o);
            if (lane >= o) t += u;
        }
        if (lane < 8) wsum[lane] = t;
    }
    __syncthreads();
    int run = ps - s + (w ? wsum[w - 1] : 0);
#pragma unroll
    for (int j = 0; j < 4; j++) {
        int i = base + j;
        if (i < n) g_off[i] = run;
        else if (i == n) g_off[n] = run;
        run += v[j];
    }
    if (tid == 0) g_bsums[blockIdx.x] = wsum[7];

    __threadfence();
    if (tid == 0) {
        int old = atomicAdd(&g_done, 1);
        isLast = (old == nb - 1);
    }
    __syncthreads();
    if (isLast) {
        int val = (tid < nb) ? ((volatile int*)g_bsums)[tid] : 0;
        sh[tid] = val;
        __syncthreads();
        for (int o = 1; o < 256; o <<= 1) {
            int t = (tid >= o) ? sh[tid - o] : 0;
            __syncthreads();
            sh[tid] += t;
            __syncthreads();
        }
        g_bsums[tid] = sh[tid] - val;
        if (tid == 0) g_done = 0;
    }
}

__global__ void k_scatter(const int* __restrict__ ei, int E) {
    int e = blockIdx.x * blockDim.x + threadIdx.x;
    if (e >= E) return;
    int s = ei[e];
    int d = ei[E + e];
    int pos = foff(d) + atomicAdd(&g_cur[d], 1);
    g_meta[pos] = make_int2(s, __float_as_int(g_dinv[s] * g_dinv[d]));
}

__global__ void k_reset(int n) {
    int i = blockIdx.x * blockDim.x + threadIdx.x;
    if (i < n) { g_deg[i] = 0; g_cur[i] = 0; }
}

// ---------------- packed f32x2 helpers ----------------
__device__ __forceinline__ unsigned long long dup2(float x) {
    unsigned long long r;
    asm("mov.b64 %0, {%1, %1};" : "=l"(r) : "f"(x));
    return r;
}
__device__ __forceinline__ void ffma2(unsigned long long& d,
                                      unsigned long long a, unsigned long long b) {
    asm("fma.rn.f32x2 %0, %1, %2, %0;" : "+l"(d) : "l"(a), "l"(b));
}
__device__ __forceinline__ float2 unpk(unsigned long long v) {
    float2 r;
    asm("mov.b64 {%0, %1}, %2;" : "=f"(r.x), "=f"(r.y) : "l"(v));
    return r;
}

// ---------------- GEMM (R10 version): g_t[n,64](fp16) = A[n,K] @ W[K,64] -----
// A == nullptr -> read g_h. 128x64 tile, 256 thr; accumulators pair ADJACENT
// ROWS (direct LDS.64 a-operand); 4 W-dup MOVs per k. fp32 math, fp16 epilogue.
template <int K>
__global__ __launch_bounds__(256) void k_gemm(const float* __restrict__ Ain,
                                              const float* __restrict__ W, int n) {
    const float* A = Ain ? Ain : g_h;
    constexpr int KC = 32;
    constexpr int PF = 2 * KC + 4;                   // 68 floats per pair-row
    __shared__ __align__(16) float Xs[64 * PF];
    __shared__ __align__(16) float Wsh[KC * 64];

    int tid = threadIdx.x;
    int row0 = blockIdx.x * 128;
    int tx = tid & 15, ty = tid >> 4;
    int c0 = tx * 4;
    int p0 = ty * 4;                                 // first row-pair

    unsigned long long acc[4][4];                    // [row-pair][col]
#pragma unroll
    for (int i = 0; i < 4; i++)
#pragma unroll
        for (int j = 0; j < 4; j++) acc[i][j] = 0ull;

    for (int kc = 0; kc < K; kc += KC) {
        __syncthreads();
#pragma unroll
        for (int it = 0; it < 4; ++it) {
            int i = tid + it * 256;          // 1024 float4 slots
            int row = i >> 3;
            int k4 = (i & 7) * 4;
            int gr = row0 + row;
            float4 v = make_float4(0.f, 0.f, 0.f, 0.f);
            if (gr < n) v = *(const float4*)&A[(size_t)gr * K + kc + k4];
            int base = (row >> 1) * PF + (row & 1);
            Xs[base + 2 * (k4 + 0)] = v.x;
            Xs[base + 2 * (k4 + 1)] = v.y;
            Xs[base + 2 * (k4 + 2)] = v.z;
            Xs[base + 2 * (k4 + 3)] = v.w;
        }
#pragma unroll
        for (int it = 0; it < 2; ++it) {
            int i = tid + it * 256;
            *(float4*)&Wsh[i * 4] = *(const float4*)&W[(size_t)kc * 64 + i * 4];
        }
        __syncthreads();

#pragma unroll
        for (int k = 0; k < KC; ++k) {
            float4 wv = *(const float4*)&Wsh[k * 64 + c0];
            unsigned long long w0 = dup2(wv.x), w1 = dup2(wv.y);
            unsigned long long w2 = dup2(wv.z), w3 = dup2(wv.w);
#pragma unroll
            for (int i = 0; i < 4; i++) {
                unsigned long long x2 =
                    *(const unsigned long long*)&Xs[(p0 + i) * PF + 2 * k];
                ffma2(acc[i][0], x2, w0);
                ffma2(acc[i][1], x2, w1);
                ffma2(acc[i][2], x2, w2);
                ffma2(acc[i][3], x2, w3);
            }
        }
    }

#pragma unroll
    for (int i = 0; i < 4; i++) {
        int gr = row0 + (p0 + i) * 2;
        float2 a0 = unpk(acc[i][0]), a1 = unpk(acc[i][1]);
        float2 a2 = unpk(acc[i][2]), a3 = unpk(acc[i][3]);
        if (gr < n) {
            __half2 h01 = __floats2half2_rn(a0.x, a1.x);
            __half2 h23 = __floats2half2_rn(a2.x, a3.x);
            *(uint2*)&g_t[(size_t)gr * 64 + c0] =
                make_uint2(*(unsigned*)&h01, *(unsigned*)&h23);
        }
        if (gr + 1 < n) {
            __half2 h01 = __floats2half2_rn(a0.y, a1.y);
            __half2 h23 = __floats2half2_rn(a2.y, a3.y);
            *(uint2*)&g_t[(size_t)(gr + 1) * 64 + c0] =
                make_uint2(*(unsigned*)&h01, *(unsigned*)&h23);
        }
    }
}

// ---------------- propagation: out[d] = sum_{e: dst=d} w_e * t[src_e]
//                   + dinv[d]^2 * t[d] (+bias) (+relu), t in fp16 -------------
// Warp per node, lane owns one half2. PIPELINED gather: ping-pong 8-edge batch
// buffers (A/B) so two batches of loads are in flight, plus next-chunk meta
// prefetch and hoisted self-loop load. Dual fp32 accumulator streams.
__global__ __launch_bounds__(256) void k_prop(float* __restrict__ outp,
                                              const float* __restrict__ bias, int relu,
                                              int n) {
    float* out = outp ? outp : g_h;
    const __half2* t2 = (const __half2*)g_t;     // row = 32 half2
    int node = (blockIdx.x * blockDim.x + threadIdx.x) >> 5;
    int lane = threadIdx.x & 31;
    if (node >= n) return;
    int beg = foff(node), end = foff(node + 1);
    const __half2* tf = t2 + lane;

    // independent early loads
    float dv = g_dinv[node];
    __half2 vself = tf[(size_t)node * 32];

    float ax0 = 0.f, ay0 = 0.f, ax1 = 0.f, ay1 = 0.f;

#define SHUF_LOAD(WARR, VARR, BB)                                              \
    _Pragma("unroll")                                                          \
    for (int i = 0; i < 8; i++) {                                              \
        int s_ = __shfl_sync(0xffffffffu, sv, (BB) + i);                       \
        WARR[i] = __shfl_sync(0xffffffffu, wv, (BB) + i);                      \
        VARR[i] = tf[(size_t)s_ * 32];                                         \
    }
#define FMA8(WARR, VARR)                                                       \
    _Pragma("unroll")                                                          \
    for (int i = 0; i < 8; i++) {                                              \
        float2 f_ = __half22float2(VARR[i]);                                   \
        if (i & 1) { ax1 = fmaf(WARR[i], f_.x, ax1);                           \
                     ay1 = fmaf(WARR[i], f_.y, ay1); }                         \
        else       { ax0 = fmaf(WARR[i], f_.x, ax0);                           \
                     ay0 = fmaf(WARR[i], f_.y, ay0); }                         \
    }

    int j = beg;
    int m = end - j; if (m > 32) m = 32;
    int sv = 0; float wv = 0.f;
    if (j < end && lane < m) {
        int2 mw = g_meta[j + lane];
        sv = mw.x; wv = __int_as_float(mw.y);
    }

    while (j < end) {
        // prefetch next chunk's meta before processing this chunk
        int jn = j + 32;
        int svn = 0; float wvn = 0.f; int mn = 0;
        if (jn < end) {
            mn = end - jn; if (mn > 32) mn = 32;
            if (lane < mn) {
                int2 mw = g_meta[jn + lane];
                svn = mw.x; wvn = __int_as_float(mw.y);
            }
        }

        int nb8 = (m + 7) >> 3;                      // 1..4 batches
        float    wA[8], wB[8];
        __half2  vA[8], vB[8];
        SHUF_LOAD(wA, vA, 0)                          // batch 0 -> A
        if (nb8 > 1) { SHUF_LOAD(wB, vB, 8) }         // batch 1 -> B (in flight)
        FMA8(wA, vA)
        if (nb8 > 2) { SHUF_LOAD(wA, vA, 16) }        // batch 2 -> A
        if (nb8 > 1) { FMA8(wB, vB) }
        if (nb8 > 3) { SHUF_LOAD(wB, vB, 24) }        // batch 3 -> B
        if (nb8 > 2) { FMA8(wA, vA) }
        if (nb8 > 3) { FMA8(wB, vB) }

        j = jn; m = mn; sv = svn; wv = wvn;
    }
#undef SHUF_LOAD
#undef FMA8

    float accx = ax0 + ax1, accy = ay0 + ay1;
    // self loop
    float2 v0 = __half22float2(vself);
    float w0 = dv * dv;
    accx = fmaf(w0, v0.x, accx);
    accy = fmaf(w0, v0.y, accy);
    if (bias) { accx += bias[2 * lane]; accy += bias[2 * lane + 1]; }
    if (relu) { accx = fmaxf(accx, 0.f); accy = fmaxf(accy, 0.f); }
    *(float2*)(out + (size_t)node * 64 + 2 * lane) = make_float2(accx, accy);
}

// ---------------- launch ----------------
extern "C" void kernel_launch(void* const* d_in, const int* in_sizes, int n_in,
                              void* d_out, int out_size) {
    const float* x     = (const float*)d_in[0];
    const int*   ei    = (const int*)d_in[1];     // int32 (JAX x64 disabled)
    const float* W_in  = (const float*)d_in[2];
    const float* b_in  = (const float*)d_in[3];
    const float* W_h   = (const float*)d_in[4];
    const float* b_h   = (const float*)d_in[5];
    const float* W_out = (const float*)d_in[6];

    int n = in_sizes[0] / 128;
    int E = in_sizes[1] / 2;

    int nb1 = (n + 1023) / 1024;
    int gb = (n + 127) / 128;
    int pb = (n + 7) / 8;

    // Fork: CSR build on side stream (init-free; k_reset of previous replay /
    // static zero-init provides zeroed g_deg/g_cur).
    cudaEventRecord(g_evA, 0);
    cudaStreamWaitEvent(g_s2, g_evA, 0);
    k_count  <<<(E + 255) / 256, 256, 0, g_s2>>>(ei, E);     // slot 1
    k_scan1f <<<nb1, 256, 0, g_s2>>>(n, nb1);                // slot 2
    k_scatter<<<(E + 255) / 256, 256, 0, g_s2>>>(ei, E);     // slot 3
    cudaEventRecord(g_evB, g_s2);

    // layer-1 GEMM overlaps CSR build — my-kernel slot 4 (ncu target)
    k_gemm<128><<<gb, 256>>>(x, W_in, n);

    // hidden reset tail on side stream (joined at the very end)
    k_reset<<<(n + 255) / 256, 256, 0, g_s2>>>(n);
    cudaEventRecord(g_evC, g_s2);

    // Join: prop needs both GEMM output and CSR
    cudaStreamWaitEvent(0, g_evB, 0);
    k_prop<<<pb, 256>>>(nullptr, b_in, 0, n);

    // hidden layers: h = relu(prop(h @ W_h[l]) + b_h[l])
    for (int l = 0; l < 3; ++l) {
        k_gemm<64><<<gb, 256>>>(nullptr, W_h + (size_t)l * 64 * 64, n);
        k_prop<<<pb, 256>>>(nullptr, b_h + (size_t)l * 64, 1, n);
    }

    // output layer: out = prop(h @ W_out), no bias, no relu
    k_gemm<64><<<gb, 256>>>(nullptr, W_out, n);
    k_prop<<<pb, 256>>>((float*)d_out, nullptr, 0, n);

    // join side stream (k_reset) so capture sees no unjoined work
    cudaStreamWaitEvent(0, g_evC, 0);
}

// round 15
// speedup vs baseline: 1.4138x; 1.1520x over previous
#include <cuda_runtime.h>
#include <cuda_fp16.h>

#define N_MAX 100000
#define E_MAX 1700000

// ---------------- static device scratch ----------------
__device__ __align__(16) __half g_t[(size_t)N_MAX * 64];  // GEMM out / prop in (fp16)
__device__ __align__(16) float  g_h[(size_t)N_MAX * 64];  // prop out (tf32-rounded fp32)
__device__ __align__(16) float  g_wr[4 * 4096];           // tf32-rounded W_h[0..2], W_out
__device__ __align__(16) int2   g_meta[E_MAX];  // CSR: (src, w-bits) per edge (by dst)
__device__ int   g_deg[N_MAX];               // RAW in-degree; zero-init, k_reset'd
__device__ int   g_cur[N_MAX];               // scatter cursors; zero-init, k_reset'd
__device__ int   g_off[N_MAX + 1];           // CSR offsets, block-LOCAL (add g_bsums)
__device__ float g_dinv[N_MAX];              // (deg+1)^-1/2
__device__ int   g_bsums[256];               // scan block sums (exclusive after scan1f)
__device__ int   g_done;                     // scan1f completion counter (self-reset)

__device__ __forceinline__ int foff(int i) {   // final CSR offset
    return g_off[i] + g_bsums[i >> 10];
}

// ---------------- side stream for fork-join overlap (created pre-baseline) ---
static cudaStream_t g_s2;
static cudaEvent_t  g_evA, g_evB, g_evC;
static struct SideInit {
    SideInit() {
        cudaStreamCreateWithFlags(&g_s2, cudaStreamNonBlocking);
        cudaEventCreateWithFlags(&g_evA, cudaEventDisableTiming);
        cudaEventCreateWithFlags(&g_evB, cudaEventDisableTiming);
        cudaEventCreateWithFlags(&g_evC, cudaEventDisableTiming);
    }
} g_side_init;

// ---------------- graph preprocessing ----------------
// edge_index is int32 (JAX x64 disabled downcasts jnp.int64 -> int32)
__global__ void k_count(const int* __restrict__ ei, int E) {
    int e = blockIdx.x * blockDim.x + threadIdx.x;
    if (e < E) atomicAdd(&g_deg[ei[E + e]], 1);
}

// scan of raw deg over 1024-elem tiles + fused dinv; LAST finishing block also
// performs the cross-block scan of g_bsums.
__global__ __launch_bounds__(256) void k_scan1f(int n, int nb) {
    __shared__ int wsum[8];
    __shared__ int sh[256];
    __shared__ int isLast;
    int tid = threadIdx.x;
    int base = blockIdx.x * 1024 + tid * 4;
    int v[4];
#pragma unroll
    for (int j = 0; j < 4; j++) {
        int i = base + j;
        int draw = (i < n) ? g_deg[i] : 0;
        v[j] = draw;
        if (i < n) g_dinv[i] = rsqrtf((float)(draw + 1));
    }
    int s = v[0] + v[1] + v[2] + v[3];
    int lane = tid & 31, w = tid >> 5;
    int ps = s;
#pragma unroll
    for (int o = 1; o < 32; o <<= 1) {
        int t = __shfl_up_sync(0xffffffffu, ps, o);
        if (lane >= o) ps += t;
    }
    if (lane == 31) wsum[w] = ps;
    __syncthreads();
    if (w == 0) {
        int t = (lane < 8) ? wsum[lane] : 0;
#pragma unroll
        for (int o = 1; o < 8; o <<= 1) {
            int u = __shfl_up_sync(0xffffffffu, t, o);
            if (lane >= o) t += u;
        }
        if (lane < 8) wsum[lane] = t;
    }
    __syncthreads();
    int run = ps - s + (w ? wsum[w - 1] : 0);
#pragma unroll
    for (int j = 0; j < 4; j++) {
        int i = base + j;
        if (i < n) g_off[i] = run;
        else if (i == n) g_off[n] = run;
        run += v[j];
    }
    if (tid == 0) g_bsums[blockIdx.x] = wsum[7];

    __threadfence();
    if (tid == 0) {
        int old = atomicAdd(&g_done, 1);
        isLast = (old == nb - 1);
    }
    __syncthreads();
    if (isLast) {
        int val = (tid < nb) ? ((volatile int*)g_bsums)[tid] : 0;
        sh[tid] = val;
        __syncthreads();
        for (int o = 1; o < 256; o <<= 1) {
            int t = (tid >= o) ? sh[tid - o] : 0;
            __syncthreads();
            sh[tid] += t;
            __syncthreads();
        }
        g_bsums[tid] = sh[tid] - val;
        if (tid == 0) g_done = 0;
    }
}

__global__ void k_scatter(const int* __restrict__ ei, int E) {
    int e = blockIdx.x * blockDim.x + threadIdx.x;
    if (e >= E) return;
    int s = ei[e];
    int d = ei[E + e];
    int pos = foff(d) + atomicAdd(&g_cur[d], 1);
    g_meta[pos] = make_int2(s, __float_as_int(g_dinv[s] * g_dinv[d]));
}

__global__ void k_reset(int n) {
    int i = blockIdx.x * blockDim.x + threadIdx.x;
    if (i < n) { g_deg[i] = 0; g_cur[i] = 0; }
}

// pre-round W_h (3x4096) + W_out (4096) to tf32 (rna) once per launch
__global__ void k_roundw(const float* __restrict__ W_h,
                         const float* __restrict__ W_out) {
    int i = blockIdx.x * blockDim.x + threadIdx.x;   // 16384 total
    float v = (i < 12288) ? W_h[i] : W_out[i - 12288];
    unsigned u;
    asm("cvt.rna.tf32.f32 %0, %1;" : "=r"(u) : "f"(v));
    g_wr[i] = __uint_as_float(u);
}

// ---------------- packed f32x2 helpers ----------------
__device__ __forceinline__ unsigned long long dup2(float x) {
    unsigned long long r;
    asm("mov.b64 %0, {%1, %1};" : "=l"(r) : "f"(x));
    return r;
}
__device__ __forceinline__ void ffma2(unsigned long long& d,
                                      unsigned long long a, unsigned long long b) {
    asm("fma.rn.f32x2 %0, %1, %2, %0;" : "+l"(d) : "l"(a), "l"(b));
}
__device__ __forceinline__ float2 unpk(unsigned long long v) {
    float2 r;
    asm("mov.b64 {%0, %1}, %2;" : "=f"(r.x), "=f"(r.y) : "l"(v));
    return r;
}

// ---------------- layer-1 GEMM (FFMA, hidden under CSR): t = x @ W_in --------
template <int K>
__global__ __launch_bounds__(256) void k_gemm(const float* __restrict__ A,
                                              const float* __restrict__ W, int n) {
    constexpr int KC = 32;
    constexpr int PF = 2 * KC + 4;                   // 68 floats per pair-row
    __shared__ __align__(16) float Xs[64 * PF];
    __shared__ __align__(16) float Wsh[KC * 64];

    int tid = threadIdx.x;
    int row0 = blockIdx.x * 128;
    int tx = tid & 15, ty = tid >> 4;
    int c0 = tx * 4;
    int p0 = ty * 4;

    unsigned long long acc[4][4];
#pragma unroll
    for (int i = 0; i < 4; i++)
#pragma unroll
        for (int j = 0; j < 4; j++) acc[i][j] = 0ull;

    for (int kc = 0; kc < K; kc += KC) {
        __syncthreads();
#pragma unroll
        for (int it = 0; it < 4; ++it) {
            int i = tid + it * 256;
            int row = i >> 3;
            int k4 = (i & 7) * 4;
            int gr = row0 + row;
            float4 v = make_float4(0.f, 0.f, 0.f, 0.f);
            if (gr < n) v = *(const float4*)&A[(size_t)gr * K + kc + k4];
            int base = (row >> 1) * PF + (row & 1);
            Xs[base + 2 * (k4 + 0)] = v.x;
            Xs[base + 2 * (k4 + 1)] = v.y;
            Xs[base + 2 * (k4 + 2)] = v.z;
            Xs[base + 2 * (k4 + 3)] = v.w;
        }
#pragma unroll
        for (int it = 0; it < 2; ++it) {
            int i = tid + it * 256;
            *(float4*)&Wsh[i * 4] = *(const float4*)&W[(size_t)kc * 64 + i * 4];
        }
        __syncthreads();

#pragma unroll
        for (int k = 0; k < KC; ++k) {
            float4 wv = *(const float4*)&Wsh[k * 64 + c0];
            unsigned long long w0 = dup2(wv.x), w1 = dup2(wv.y);
            unsigned long long w2 = dup2(wv.z), w3 = dup2(wv.w);
#pragma unroll
            for (int i = 0; i < 4; i++) {
                unsigned long long x2 =
                    *(const unsigned long long*)&Xs[(p0 + i) * PF + 2 * k];
                ffma2(acc[i][0], x2, w0);
                ffma2(acc[i][1], x2, w1);
                ffma2(acc[i][2], x2, w2);
                ffma2(acc[i][3], x2, w3);
            }
        }
    }

#pragma unroll
    for (int i = 0; i < 4; i++) {
        int gr = row0 + (p0 + i) * 2;
        float2 a0 = unpk(acc[i][0]), a1 = unpk(acc[i][1]);
        float2 a2 = unpk(acc[i][2]), a3 = unpk(acc[i][3]);
        if (gr < n) {
            __half2 h01 = __floats2half2_rn(a0.x, a1.x);
            __half2 h23 = __floats2half2_rn(a2.x, a3.x);
            *(uint2*)&g_t[(size_t)gr * 64 + c0] =
                make_uint2(*(unsigned*)&h01, *(unsigned*)&h23);
        }
        if (gr + 1 < n) {
            __half2 h01 = __floats2half2_rn(a0.y, a1.y);
            __half2 h23 = __floats2half2_rn(a2.y, a3.y);
            *(uint2*)&g_t[(size_t)(gr + 1) * 64 + c0] =
                make_uint2(*(unsigned*)&h01, *(unsigned*)&h23);
        }
    }
}

// ---------------- tensor-core GEMM: g_t[n,64](fp16) = g_h[n,64] @ Wr[64,64] --
// mma.sync m16n8k8 tf32 (inputs pre-rounded: g_h by prop epilogue, Wr by
// k_roundw). wsel picks the weight slice IN DEVICE CODE (g_wr is a __device__
// symbol — its address must never be taken host-side). 128x64 tile, 8 warps.
__global__ __launch_bounds__(256) void k_mma(int wsel, int n) {
    constexpr int AP = 36;
    constexpr int BP = 72;
    __shared__ __align__(16) float As[128 * AP];   // 18.4 KB
    __shared__ __align__(16) float Bs[32 * BP];    //  9.2 KB

    const float* Wr = g_wr + (size_t)wsel * 4096;

    int tid = threadIdx.x;
    int lane = tid & 31, wp = tid >> 5;
    int row0 = blockIdx.x * 128;
    int g = lane >> 2, tg = lane & 3;              // groupID, thread-in-group

    float c[8][4];
#pragma unroll
    for (int i = 0; i < 8; i++)
#pragma unroll
        for (int j = 0; j < 4; j++) c[i][j] = 0.f;

    for (int kc = 0; kc < 64; kc += 32) {
        __syncthreads();
        // A chunk 128x32 (coalesced float4)
#pragma unroll
        for (int it = 0; it < 4; ++it) {
            int i = tid + it * 256;
            int row = i >> 3, k4 = (i & 7) * 4;
            int gr = row0 + row;
            float4 v = make_float4(0.f, 0.f, 0.f, 0.f);
            if (gr < n) v = *(const float4*)&g_h[(size_t)gr * 64 + kc + k4];
            *(float4*)&As[row * AP + k4] = v;
        }
        // B chunk 32x64
#pragma unroll
        for (int it = 0; it < 2; ++it) {
            int i = tid + it * 256;
            int row = i >> 4, c4 = (i & 15) * 4;
            float4 v = *(const float4*)&Wr[(size_t)(kc + row) * 64 + c4];
            *(float4*)&Bs[row * BP + c4] = v;
        }
        __syncthreads();

#pragma unroll
        for (int ks = 0; ks < 4; ++ks) {
            int k0 = ks * 8;
            const float* arow = &As[(wp * 16 + g) * AP + k0 + tg];
            unsigned a0 = __float_as_uint(arow[0]);
            unsigned a1 = __float_as_uint(arow[8 * AP]);
            unsigned a2 = __float_as_uint(arow[4]);
            unsigned a3 = __float_as_uint(arow[8 * AP + 4]);
#pragma unroll
            for (int nt = 0; nt < 8; ++nt) {
                unsigned b0 = __float_as_uint(Bs[(k0 + tg) * BP + nt * 8 + g]);
                unsigned b1 = __float_as_uint(Bs[(k0 + tg + 4) * BP + nt * 8 + g]);
                asm volatile(
                    "mma.sync.aligned.m16n8k8.row.col.f32.tf32.tf32.f32 "
                    "{%0,%1,%2,%3}, {%4,%5,%6,%7}, {%8,%9}, {%0,%1,%2,%3};"
                    : "+f"(c[nt][0]), "+f"(c[nt][1]), "+f"(c[nt][2]), "+f"(c[nt][3])
                    : "r"(a0), "r"(a1), "r"(a2), "r"(a3), "r"(b0), "r"(b1));
            }
        }
    }

    int r0 = row0 + wp * 16 + g;
#pragma unroll
    for (int nt = 0; nt < 8; ++nt) {
        int col = nt * 8 + 2 * tg;
        if (r0 < n) {
            __half2 h = __floats2half2_rn(c[nt][0], c[nt][1]);
            *(unsigned*)&g_t[(size_t)r0 * 64 + col] = *(unsigned*)&h;
        }
        if (r0 + 8 < n) {
            __half2 h = __floats2half2_rn(c[nt][2], c[nt][3]);
            *(unsigned*)&g_t[(size_t)(r0 + 8) * 64 + col] = *(unsigned*)&h;
        }
    }
}

// ---------------- propagation (R10 version + tf32-rna epilogue for g_h) ------
// out[d] = sum w_e * t[src_e] + dinv^2 * t[d] (+bias)(+relu); t fp16.
// Warp per node, lane owns one half2, batch-8 MLP gather, no atomics.
__global__ __launch_bounds__(256) void k_prop(float* __restrict__ outp,
                                              const float* __restrict__ bias, int relu,
                                              int n) {
    float* out = outp ? outp : g_h;
    const __half2* t2 = (const __half2*)g_t;
    int node = (blockIdx.x * blockDim.x + threadIdx.x) >> 5;
    int lane = threadIdx.x & 31;
    if (node >= n) return;
    int beg = foff(node), end = foff(node + 1);
    const __half2* tf = t2 + lane;

    float ax0 = 0.f, ay0 = 0.f, ax1 = 0.f, ay1 = 0.f;
    for (int j = beg; j < end; j += 32) {
        int m = end - j;
        if (m > 32) m = 32;
        int sv = 0;
        float wv = 0.f;
        if (lane < m) {
            int2 mw = g_meta[j + lane];
            sv = mw.x;
            wv = __int_as_float(mw.y);
        }
        int nb8 = (m + 7) >> 3;
        for (int b = 0; b < nb8; ++b) {
            int bb = b * 8;
            int s[8];
            float w[8];
            __half2 v[8];
#pragma unroll
            for (int i = 0; i < 8; i++) {
                s[i] = __shfl_sync(0xffffffffu, sv, bb + i);
                w[i] = __shfl_sync(0xffffffffu, wv, bb + i);
            }
#pragma unroll
            for (int i = 0; i < 8; i++) v[i] = tf[(size_t)s[i] * 32];
#pragma unroll
            for (int i = 0; i < 8; i++) {
                float2 f = __half22float2(v[i]);
                if (i & 1) { ax1 = fmaf(w[i], f.x, ax1); ay1 = fmaf(w[i], f.y, ay1); }
                else       { ax0 = fmaf(w[i], f.x, ax0); ay0 = fmaf(w[i], f.y, ay0); }
            }
        }
    }
    float accx = ax0 + ax1, accy = ay0 + ay1;
    float dv = g_dinv[node];
    float2 v0 = __half22float2(tf[(size_t)node * 32]);
    float w0 = dv * dv;
    accx = fmaf(w0, v0.x, accx);
    accy = fmaf(w0, v0.y, accy);
    if (bias) { accx += bias[2 * lane]; accy += bias[2 * lane + 1]; }
    if (relu) { accx = fmaxf(accx, 0.f); accy = fmaxf(accy, 0.f); }
    if (!outp) {
        // writing g_h (tensor-core GEMM input): round to tf32 (rna) here,
        // where issue slots are idle, so k_mma needs no conversions.
        unsigned ux, uy;
        asm("cvt.rna.tf32.f32 %0, %1;" : "=r"(ux) : "f"(accx));
        asm("cvt.rna.tf32.f32 %0, %1;" : "=r"(uy) : "f"(accy));
        accx = __uint_as_float(ux);
        accy = __uint_as_float(uy);
    }
    *(float2*)(out + (size_t)node * 64 + 2 * lane) = make_float2(accx, accy);
}

// ---------------- launch ----------------
extern "C" void kernel_launch(void* const* d_in, const int* in_sizes, int n_in,
                              void* d_out, int out_size) {
    const float* x     = (const float*)d_in[0];
    const int*   ei    = (const int*)d_in[1];     // int32 (JAX x64 disabled)
    const float* W_in  = (const float*)d_in[2];
    const float* b_in  = (const float*)d_in[3];
    const float* W_h   = (const float*)d_in[4];
    const float* b_h   = (const float*)d_in[5];
    const float* W_out = (const float*)d_in[6];

    int n = in_sizes[0] / 128;
    int E = in_sizes[1] / 2;

    int nb1 = (n + 1023) / 1024;
    int gb = (n + 127) / 128;
    int pb = (n + 7) / 8;

    // Fork: CSR build + weight rounding on side stream.
    cudaEventRecord(g_evA, 0);
    cudaStreamWaitEvent(g_s2, g_evA, 0);
    k_count  <<<(E + 255) / 256, 256, 0, g_s2>>>(ei, E);     // slot 1
    k_scan1f <<<nb1, 256, 0, g_s2>>>(n, nb1);                // slot 2
    k_scatter<<<(E + 255) / 256, 256, 0, g_s2>>>(ei, E);     // slot 3

    // layer-1 GEMM (FFMA) overlaps CSR build — slot 4 (ncu target)
    k_gemm<128><<<gb, 256>>>(x, W_in, n);

    k_roundw <<<64, 256, 0, g_s2>>>(W_h, W_out);
    cudaEventRecord(g_evB, g_s2);
    k_reset  <<<(n + 255) / 256, 256, 0, g_s2>>>(n);         // hidden tail work
    cudaEventRecord(g_evC, g_s2);

    // Join: prop needs CSR (+ roundw for the mma that follows)
    cudaStreamWaitEvent(0, g_evB, 0);
    k_prop<<<pb, 256>>>(nullptr, b_in, 0, n);                // prop1 -> g_h (tf32)

    // hidden + output GEMMs on tensor cores (weight slice chosen in-device)
    k_mma<<<gb, 256>>>(0, n);                                // gemm(Wh0) -> t
    k_prop<<<pb, 256>>>(nullptr, b_h, 1, n);                 // prop2
    k_mma<<<gb, 256>>>(1, n);                                // gemm(Wh1)
    k_prop<<<pb, 256>>>(nullptr, b_h + 64, 1, n);            // prop3
    k_mma<<<gb, 256>>>(2, n);                                // gemm(Wh2)
    k_prop<<<pb, 256>>>(nullptr, b_h + 128, 1, n);           // prop4
    k_mma<<<gb, 256>>>(3, n);                                // gemm(Wout)
    k_prop<<<pb, 256>>>((float*)d_out, nullptr, 0, n);       // prop5 -> out

    // join side stream (k_reset) so capture sees no unjoined work
    cudaStreamWaitEvent(0, g_evC, 0);
}

// round 16
// speedup vs baseline: 1.4715x; 1.0408x over previous
#include <cuda_runtime.h>
#include <cuda_fp16.h>

#define N_MAX 100000
#define E_MAX 1700000

// ---------------- static device scratch ----------------
__device__ __align__(16) __half g_t[(size_t)N_MAX * 64];  // GEMM out / prop in (fp16)
__device__ __align__(16) float  g_h[(size_t)N_MAX * 64];  // prop out (tf32-rounded fp32)
__device__ __align__(16) float  g_wr[4 * 4096];           // tf32-rounded W_h[0..2], W_out
__device__ __align__(16) int2   g_meta[E_MAX];  // CSR: (src, w-bits) per edge (by dst)
__device__ int   g_deg[N_MAX];               // RAW in-degree; zero-init, k_reset'd
__device__ int   g_cur[N_MAX];               // scatter cursors; zero-init, k_reset'd
__device__ int   g_off[N_MAX + 1];           // CSR offsets, block-LOCAL (add g_bsums)
__device__ float g_dinv[N_MAX];              // (deg+1)^-1/2
__device__ int   g_bsums[256];               // scan block sums (exclusive after scan1f)
__device__ int   g_done;                     // scan1f completion counter (self-reset)

__device__ __forceinline__ int foff(int i) {   // final CSR offset
    return g_off[i] + g_bsums[i >> 10];
}

__device__ __forceinline__ float rna_tf32(float v) {
    unsigned u;
    asm("cvt.rna.tf32.f32 %0, %1;" : "=r"(u) : "f"(v));
    return __uint_as_float(u);
}

// ---------------- side stream for fork-join overlap (created pre-baseline) ---
static cudaStream_t g_s2;
static cudaEvent_t  g_evA, g_evB, g_evC;
static struct SideInit {
    SideInit() {
        cudaStreamCreateWithFlags(&g_s2, cudaStreamNonBlocking);
        cudaEventCreateWithFlags(&g_evA, cudaEventDisableTiming);
        cudaEventCreateWithFlags(&g_evB, cudaEventDisableTiming);
        cudaEventCreateWithFlags(&g_evC, cudaEventDisableTiming);
    }
} g_side_init;

// ---------------- graph preprocessing ----------------
// edge_index is int32 (JAX x64 disabled downcasts jnp.int64 -> int32)
__global__ void k_count(const int* __restrict__ ei, int E) {
    int e = blockIdx.x * blockDim.x + threadIdx.x;
    if (e < E) atomicAdd(&g_deg[ei[E + e]], 1);
}

// scan of raw deg over 1024-elem tiles + fused dinv; LAST finishing block also
// performs the cross-block scan of g_bsums.
__global__ __launch_bounds__(256) void k_scan1f(int n, int nb) {
    __shared__ int wsum[8];
    __shared__ int sh[256];
    __shared__ int isLast;
    int tid = threadIdx.x;
    int base = blockIdx.x * 1024 + tid * 4;
    int v[4];
#pragma unroll
    for (int j = 0; j < 4; j++) {
        int i = base + j;
        int draw = (i < n) ? g_deg[i] : 0;
        v[j] = draw;
        if (i < n) g_dinv[i] = rsqrtf((float)(draw + 1));
    }
    int s = v[0] + v[1] + v[2] + v[3];
    int lane = tid & 31, w = tid >> 5;
    int ps = s;
#pragma unroll
    for (int o = 1; o < 32; o <<= 1) {
        int t = __shfl_up_sync(0xffffffffu, ps, o);
        if (lane >= o) ps += t;
    }
    if (lane == 31) wsum[w] = ps;
    __syncthreads();
    if (w == 0) {
        int t = (lane < 8) ? wsum[lane] : 0;
#pragma unroll
        for (int o = 1; o < 8; o <<= 1) {
            int u = __shfl_up_sync(0xffffffffu, t, o);
            if (lane >= o) t += u;
        }
        if (lane < 8) wsum[lane] = t;
    }
    __syncthreads();
    int run = ps - s + (w ? wsum[w - 1] : 0);
#pragma unroll
    for (int j = 0; j < 4; j++) {
        int i = base + j;
        if (i < n) g_off[i] = run;
        else if (i == n) g_off[n] = run;
        run += v[j];
    }
    if (tid == 0) g_bsums[blockIdx.x] = wsum[7];

    __threadfence();
    if (tid == 0) {
        int old = atomicAdd(&g_done, 1);
        isLast = (old == nb - 1);
    }
    __syncthreads();
    if (isLast) {
        int val = (tid < nb) ? ((volatile int*)g_bsums)[tid] : 0;
        sh[tid] = val;
        __syncthreads();
        for (int o = 1; o < 256; o <<= 1) {
            int t = (tid >= o) ? sh[tid - o] : 0;
            __syncthreads();
            sh[tid] += t;
            __syncthreads();
        }
        g_bsums[tid] = sh[tid] - val;
        if (tid == 0) g_done = 0;
    }
}

__global__ void k_scatter(const int* __restrict__ ei, int E) {
    int e = blockIdx.x * blockDim.x + threadIdx.x;
    if (e >= E) return;
    int s = ei[e];
    int d = ei[E + e];
    int pos = foff(d) + atomicAdd(&g_cur[d], 1);
    g_meta[pos] = make_int2(s, __float_as_int(g_dinv[s] * g_dinv[d]));
}

__global__ void k_reset(int n) {
    int i = blockIdx.x * blockDim.x + threadIdx.x;
    if (i < n) { g_deg[i] = 0; g_cur[i] = 0; }
}

// pre-round W_h (3x4096) + W_out (4096) to tf32 (rna) once per launch
__global__ void k_roundw(const float* __restrict__ W_h,
                         const float* __restrict__ W_out) {
    int i = blockIdx.x * blockDim.x + threadIdx.x;   // 16384 total
    float v = (i < 12288) ? W_h[i] : W_out[i - 12288];
    g_wr[i] = rna_tf32(v);
}

// ---------------- layer-1 GEMM on tensor cores: g_t = x[n,128] @ W_in[128,64]
// tf32 m16n8k8; x and W_in are rna-rounded ONCE during smem staging.
__global__ __launch_bounds__(256) void k_mma1(const float* __restrict__ A,
                                              const float* __restrict__ W, int n) {
    constexpr int AP = 36;
    constexpr int BP = 72;
    __shared__ __align__(16) float As[128 * AP];   // 18.4 KB
    __shared__ __align__(16) float Bs[32 * BP];    //  9.2 KB

    int tid = threadIdx.x;
    int lane = tid & 31, wp = tid >> 5;
    int row0 = blockIdx.x * 128;
    int g = lane >> 2, tg = lane & 3;

    float c[8][4];
#pragma unroll
    for (int i = 0; i < 8; i++)
#pragma unroll
        for (int j = 0; j < 4; j++) c[i][j] = 0.f;

    for (int kc = 0; kc < 128; kc += 32) {
        __syncthreads();
        // A chunk 128x32 (x, row stride 128), rna -> tf32 at staging
#pragma unroll
        for (int it = 0; it < 4; ++it) {
            int i = tid + it * 256;
            int row = i >> 3, k4 = (i & 7) * 4;
            int gr = row0 + row;
            float4 v = make_float4(0.f, 0.f, 0.f, 0.f);
            if (gr < n) v = *(const float4*)&A[(size_t)gr * 128 + kc + k4];
            v.x = rna_tf32(v.x); v.y = rna_tf32(v.y);
            v.z = rna_tf32(v.z); v.w = rna_tf32(v.w);
            *(float4*)&As[row * AP + k4] = v;
        }
        // B chunk 32x64 (W_in), rna -> tf32 at staging
#pragma unroll
        for (int it = 0; it < 2; ++it) {
            int i = tid + it * 256;
            int row = i >> 4, c4 = (i & 15) * 4;
            float4 v = *(const float4*)&W[(size_t)(kc + row) * 64 + c4];
            v.x = rna_tf32(v.x); v.y = rna_tf32(v.y);
            v.z = rna_tf32(v.z); v.w = rna_tf32(v.w);
            *(float4*)&Bs[row * BP + c4] = v;
        }
        __syncthreads();

#pragma unroll
        for (int ks = 0; ks < 4; ++ks) {
            int k0 = ks * 8;
            const float* arow = &As[(wp * 16 + g) * AP + k0 + tg];
            unsigned a0 = __float_as_uint(arow[0]);
            unsigned a1 = __float_as_uint(arow[8 * AP]);
            unsigned a2 = __float_as_uint(arow[4]);
            unsigned a3 = __float_as_uint(arow[8 * AP + 4]);
#pragma unroll
            for (int nt = 0; nt < 8; ++nt) {
                unsigned b0 = __float_as_uint(Bs[(k0 + tg) * BP + nt * 8 + g]);
                unsigned b1 = __float_as_uint(Bs[(k0 + tg + 4) * BP + nt * 8 + g]);
                asm volatile(
                    "mma.sync.aligned.m16n8k8.row.col.f32.tf32.tf32.f32 "
                    "{%0,%1,%2,%3}, {%4,%5,%6,%7}, {%8,%9}, {%0,%1,%2,%3};"
                    : "+f"(c[nt][0]), "+f"(c[nt][1]), "+f"(c[nt][2]), "+f"(c[nt][3])
                    : "r"(a0), "r"(a1), "r"(a2), "r"(a3), "r"(b0), "r"(b1));
            }
        }
    }

    int r0 = row0 + wp * 16 + g;
#pragma unroll
    for (int nt = 0; nt < 8; ++nt) {
        int col = nt * 8 + 2 * tg;
        if (r0 < n) {
            __half2 h = __floats2half2_rn(c[nt][0], c[nt][1]);
            *(unsigned*)&g_t[(size_t)r0 * 64 + col] = *(unsigned*)&h;
        }
        if (r0 + 8 < n) {
            __half2 h = __floats2half2_rn(c[nt][2], c[nt][3]);
            *(unsigned*)&g_t[(size_t)(r0 + 8) * 64 + col] = *(unsigned*)&h;
        }
    }
}

// ---------------- tensor-core GEMM: g_t[n,64](fp16) = g_h[n,64] @ Wr[64,64] --
// Inputs pre-rounded (g_h by prop epilogue, Wr by k_roundw). wsel picks the
// weight slice IN DEVICE CODE (g_wr is a __device__ symbol).
__global__ __launch_bounds__(256) void k_mma(int wsel, int n) {
    constexpr int AP = 36;
    constexpr int BP = 72;
    __shared__ __align__(16) float As[128 * AP];
    __shared__ __align__(16) float Bs[32 * BP];

    const float* Wr = g_wr + (size_t)wsel * 4096;

    int tid = threadIdx.x;
    int lane = tid & 31, wp = tid >> 5;
    int row0 = blockIdx.x * 128;
    int g = lane >> 2, tg = lane & 3;

    float c[8][4];
#pragma unroll
    for (int i = 0; i < 8; i++)
#pragma unroll
        for (int j = 0; j < 4; j++) c[i][j] = 0.f;

    for (int kc = 0; kc < 64; kc += 32) {
        __syncthreads();
#pragma unroll
        for (int it = 0; it < 4; ++it) {
            int i = tid + it * 256;
            int row = i >> 3, k4 = (i & 7) * 4;
            int gr = row0 + row;
            float4 v = make_float4(0.f, 0.f, 0.f, 0.f);
            if (gr < n) v = *(const float4*)&g_h[(size_t)gr * 64 + kc + k4];
            *(float4*)&As[row * AP + k4] = v;
        }
#pragma unroll
        for (int it = 0; it < 2; ++it) {
            int i = tid + it * 256;
            int row = i >> 4, c4 = (i & 15) * 4;
            float4 v = *(const float4*)&Wr[(size_t)(kc + row) * 64 + c4];
            *(float4*)&Bs[row * BP + c4] = v;
        }
        __syncthreads();

#pragma unroll
        for (int ks = 0; ks < 4; ++ks) {
            int k0 = ks * 8;
            const float* arow = &As[(wp * 16 + g) * AP + k0 + tg];
            unsigned a0 = __float_as_uint(arow[0]);
            unsigned a1 = __float_as_uint(arow[8 * AP]);
            unsigned a2 = __float_as_uint(arow[4]);
            unsigned a3 = __float_as_uint(arow[8 * AP + 4]);
#pragma unroll
            for (int nt = 0; nt < 8; ++nt) {
                unsigned b0 = __float_as_uint(Bs[(k0 + tg) * BP + nt * 8 + g]);
                unsigned b1 = __float_as_uint(Bs[(k0 + tg + 4) * BP + nt * 8 + g]);
                asm volatile(
                    "mma.sync.aligned.m16n8k8.row.col.f32.tf32.tf32.f32 "
                    "{%0,%1,%2,%3}, {%4,%5,%6,%7}, {%8,%9}, {%0,%1,%2,%3};"
                    : "+f"(c[nt][0]), "+f"(c[nt][1]), "+f"(c[nt][2]), "+f"(c[nt][3])
                    : "r"(a0), "r"(a1), "r"(a2), "r"(a3), "r"(b0), "r"(b1));
            }
        }
    }

    int r0 = row0 + wp * 16 + g;
#pragma unroll
    for (int nt = 0; nt < 8; ++nt) {
        int col = nt * 8 + 2 * tg;
        if (r0 < n) {
            __half2 h = __floats2half2_rn(c[nt][0], c[nt][1]);
            *(unsigned*)&g_t[(size_t)r0 * 64 + col] = *(unsigned*)&h;
        }
        if (r0 + 8 < n) {
            __half2 h = __floats2half2_rn(c[nt][2], c[nt][3]);
            *(unsigned*)&g_t[(size_t)(r0 + 8) * 64 + col] = *(unsigned*)&h;
        }
    }
}

// ---------------- propagation (64-thread blocks to kill block-tail waves) ----
// out[d] = sum w_e * t[src_e] + dinv^2 * t[d] (+bias)(+relu); t fp16.
// Warp per node, 2 nodes per block, batch-8 MLP gather, inline shuffle consume.
__global__ __launch_bounds__(64) void k_prop(float* __restrict__ outp,
                                             const float* __restrict__ bias, int relu,
                                             int n) {
    float* out = outp ? outp : g_h;
    const __half2* t2 = (const __half2*)g_t;
    int node = (blockIdx.x * 64 + threadIdx.x) >> 5;
    int lane = threadIdx.x & 31;
    if (node >= n) return;
    int beg = foff(node), end = foff(node + 1);
    const __half2* tf = t2 + lane;

    float ax0 = 0.f, ay0 = 0.f, ax1 = 0.f, ay1 = 0.f;
    for (int j = beg; j < end; j += 32) {
        int m = end - j;
        if (m > 32) m = 32;
        int sv = 0;
        float wv = 0.f;
        if (lane < m) {
            int2 mw = g_meta[j + lane];
            sv = mw.x;
            wv = __int_as_float(mw.y);
        }
        int nb8 = (m + 7) >> 3;
        for (int b = 0; b < nb8; ++b) {
            int bb = b * 8;
            float w[8];
            __half2 v[8];
#pragma unroll
            for (int i = 0; i < 8; i++) {
                int s_ = __shfl_sync(0xffffffffu, sv, bb + i);
                w[i] = __shfl_sync(0xffffffffu, wv, bb + i);
                v[i] = tf[(size_t)s_ * 32];
            }
#pragma unroll
            for (int i = 0; i < 8; i++) {
                float2 f = __half22float2(v[i]);
                if (i & 1) { ax1 = fmaf(w[i], f.x, ax1); ay1 = fmaf(w[i], f.y, ay1); }
                else       { ax0 = fmaf(w[i], f.x, ax0); ay0 = fmaf(w[i], f.y, ay0); }
            }
        }
    }
    float accx = ax0 + ax1, accy = ay0 + ay1;
    float dv = g_dinv[node];
    float2 v0 = __half22float2(tf[(size_t)node * 32]);
    float w0 = dv * dv;
    accx = fmaf(w0, v0.x, accx);
    accy = fmaf(w0, v0.y, accy);
    if (bias) { accx += bias[2 * lane]; accy += bias[2 * lane + 1]; }
    if (relu) { accx = fmaxf(accx, 0.f); accy = fmaxf(accy, 0.f); }
    if (!outp) {
        accx = rna_tf32(accx);   // g_h feeds tensor-core GEMM: round here
        accy = rna_tf32(accy);
    }
    *(float2*)(out + (size_t)node * 64 + 2 * lane) = make_float2(accx, accy);
}

// ---------------- launch ----------------
extern "C" void kernel_launch(void* const* d_in, const int* in_sizes, int n_in,
                              void* d_out, int out_size) {
    const float* x     = (const float*)d_in[0];
    const int*   ei    = (const int*)d_in[1];     // int32 (JAX x64 disabled)
    const float* W_in  = (const float*)d_in[2];
    const float* b_in  = (const float*)d_in[3];
    const float* W_h   = (const float*)d_in[4];
    const float* b_h   = (const float*)d_in[5];
    const float* W_out = (const float*)d_in[6];

    int n = in_sizes[0] / 128;
    int E = in_sizes[1] / 2;

    int nb1 = (n + 1023) / 1024;
    int gb = (n + 127) / 128;
    int pb = (n + 1) / 2;        // 64-thread prop blocks, 2 nodes each

    // Fork: CSR build + weight rounding on side stream.
    cudaEventRecord(g_evA, 0);
    cudaStreamWaitEvent(g_s2, g_evA, 0);
    k_count  <<<(E + 255) / 256, 256, 0, g_s2>>>(ei, E);     // slot 1
    k_scan1f <<<nb1, 256, 0, g_s2>>>(n, nb1);                // slot 2
    k_scatter<<<(E + 255) / 256, 256, 0, g_s2>>>(ei, E);     // slot 3

    // layer-1 GEMM on tensor cores, overlaps CSR — slot 4 (ncu target)
    k_mma1<<<gb, 256>>>(x, W_in, n);

    k_roundw <<<64, 256, 0, g_s2>>>(W_h, W_out);
    cudaEventRecord(g_evB, g_s2);                            // CSR + roundw done
    k_reset  <<<(n + 255) / 256, 256, 0, g_s2>>>(n);         // hidden tail work
    cudaEventRecord(g_evC, g_s2);

    // Join: prop needs CSR; subsequent mma needs roundw (covered by evB)
    cudaStreamWaitEvent(0, g_evB, 0);
    k_prop<<<pb, 64>>>(nullptr, b_in, 0, n);                 // prop1 -> g_h (tf32)

    k_mma<<<gb, 256>>>(0, n);                                // gemm(Wh0) -> t
    k_prop<<<pb, 64>>>(nullptr, b_h, 1, n);                  // prop2
    k_mma<<<gb, 256>>>(1, n);                                // gemm(Wh1)
    k_prop<<<pb, 64>>>(nullptr, b_h + 64, 1, n);             // prop3
    k_mma<<<gb, 256>>>(2, n);                                // gemm(Wh2)
    k_prop<<<pb, 64>>>(nullptr, b_h + 128, 1, n);            // prop4
    k_mma<<<gb, 256>>>(3, n);                                // gemm(Wout)
    k_prop<<<pb, 64>>>((float*)d_out, nullptr, 0, n);        // prop5 -> out

    // join side stream (k_reset) so capture sees no unjoined work
    cudaStreamWaitEvent(0, g_evC, 0);
}

// round 17
// speedup vs baseline: 1.5111x; 1.0269x over previous
#include <cuda_runtime.h>
#include <cuda_fp16.h>

#define N_MAX 100000
#define E_MAX 1700000

// ---------------- static device scratch ----------------
__device__ __align__(16) __half g_t[(size_t)N_MAX * 64];  // GEMM out / prop in (fp16)
__device__ __align__(16) float  g_h[(size_t)N_MAX * 64];  // prop out (tf32-rounded fp32)
__device__ __align__(16) float  g_wr[4 * 4096];           // tf32-rounded W_h[0..2], W_out
__device__ __align__(16) int2   g_meta[E_MAX];  // CSR: (src, w-bits) per edge (by dst)
__device__ int   g_deg[N_MAX];               // RAW in-degree; zero-init, k_reset'd
__device__ int   g_cur[N_MAX];               // scatter cursors; zero-init, k_reset'd
__device__ int   g_off[N_MAX + 1];           // CSR offsets, block-LOCAL (add g_bsums)
__device__ float g_dinv[N_MAX];              // (deg+1)^-1/2
__device__ int   g_bsums[256];               // scan block sums (exclusive after scan1f)
__device__ int   g_done;                     // scan1f completion counter (self-reset)

__device__ __forceinline__ int foff(int i) {   // final CSR offset
    return g_off[i] + g_bsums[i >> 10];
}

__device__ __forceinline__ float rna_tf32(float v) {
    unsigned u;
    asm("cvt.rna.tf32.f32 %0, %1;" : "=r"(u) : "f"(v));
    return __uint_as_float(u);
}

// ---------------- side stream for fork-join overlap (created pre-baseline) ---
static cudaStream_t g_s2;
static cudaEvent_t  g_evA, g_evB, g_evC;
static struct SideInit {
    SideInit() {
        cudaStreamCreateWithFlags(&g_s2, cudaStreamNonBlocking);
        cudaEventCreateWithFlags(&g_evA, cudaEventDisableTiming);
        cudaEventCreateWithFlags(&g_evB, cudaEventDisableTiming);
        cudaEventCreateWithFlags(&g_evC, cudaEventDisableTiming);
    }
} g_side_init;

// ---------------- graph preprocessing ----------------
// edge_index is int32 (JAX x64 disabled downcasts jnp.int64 -> int32)
__global__ void k_count(const int* __restrict__ ei, int E) {
    int e = blockIdx.x * blockDim.x + threadIdx.x;
    if (e < E) atomicAdd(&g_deg[ei[E + e]], 1);
}

// scan of raw deg over 1024-elem tiles + fused dinv; LAST finishing block also
// performs the cross-block scan of g_bsums.
__global__ __launch_bounds__(256) void k_scan1f(int n, int nb) {
    __shared__ int wsum[8];
    __shared__ int sh[256];
    __shared__ int isLast;
    int tid = threadIdx.x;
    int base = blockIdx.x * 1024 + tid * 4;
    int v[4];
#pragma unroll
    for (int j = 0; j < 4; j++) {
        int i = base + j;
        int draw = (i < n) ? g_deg[i] : 0;
        v[j] = draw;
        if (i < n) g_dinv[i] = rsqrtf((float)(draw + 1));
    }
    int s = v[0] + v[1] + v[2] + v[3];
    int lane = tid & 31, w = tid >> 5;
    int ps = s;
#pragma unroll
    for (int o = 1; o < 32; o <<= 1) {
        int t = __shfl_up_sync(0xffffffffu, ps, o);
        if (lane >= o) ps += t;
    }
    if (lane == 31) wsum[w] = ps;
    __syncthreads();
    if (w == 0) {
        int t = (lane < 8) ? wsum[lane] : 0;
#pragma unroll
        for (int o = 1; o < 8; o <<= 1) {
            int u = __shfl_up_sync(0xffffffffu, t, o);
            if (lane >= o) t += u;
        }
        if (lane < 8) wsum[lane] = t;
    }
    __syncthreads();
    int run = ps - s + (w ? wsum[w - 1] : 0);
#pragma unroll
    for (int j = 0; j < 4; j++) {
        int i = base + j;
        if (i < n) g_off[i] = run;
        else if (i == n) g_off[n] = run;
        run += v[j];
    }
    if (tid == 0) g_bsums[blockIdx.x] = wsum[7];

    __threadfence();
    if (tid == 0) {
        int old = atomicAdd(&g_done, 1);
        isLast = (old == nb - 1);
    }
    __syncthreads();
    if (isLast) {
        int val = (tid < nb) ? ((volatile int*)g_bsums)[tid] : 0;
        sh[tid] = val;
        __syncthreads();
        for (int o = 1; o < 256; o <<= 1) {
            int t = (tid >= o) ? sh[tid - o] : 0;
            __syncthreads();
            sh[tid] += t;
            __syncthreads();
        }
        g_bsums[tid] = sh[tid] - val;
        if (tid == 0) g_done = 0;
    }
}

__global__ void k_scatter(const int* __restrict__ ei, int E) {
    int e = blockIdx.x * blockDim.x + threadIdx.x;
    if (e >= E) return;
    int s = ei[e];
    int d = ei[E + e];
    int pos = foff(d) + atomicAdd(&g_cur[d], 1);
    g_meta[pos] = make_int2(s, __float_as_int(g_dinv[s] * g_dinv[d]));
}

__global__ void k_reset(int n) {
    int i = blockIdx.x * blockDim.x + threadIdx.x;
    if (i < n) { g_deg[i] = 0; g_cur[i] = 0; }
}

// pre-round W_h (3x4096) + W_out (4096) to tf32 (rna) once per launch
__global__ void k_roundw(const float* __restrict__ W_h,
                         const float* __restrict__ W_out) {
    int i = blockIdx.x * blockDim.x + threadIdx.x;   // 16384 total
    float v = (i < 12288) ? W_h[i] : W_out[i - 12288];
    g_wr[i] = rna_tf32(v);
}

// ---------------- shared mma tile core ----------------
// Bs fragment-major layout: Bs[k*BP + g*12 + nt], logical col = nt*8 + g.
// Per ks-step a thread's 16 B-frag values come from 4 conflict-free LDS.128.
#define MMA_AP 36
#define MMA_BP 104

__device__ __forceinline__ void mma_chunk(const float* As, const float* Bs,
                                          int wp, int g, int tg, float c[8][4]) {
#pragma unroll
    for (int ks = 0; ks < 4; ++ks) {
        int k0 = ks * 8;
        const float* arow = &As[(wp * 16 + g) * MMA_AP + k0 + tg];
        unsigned a0 = __float_as_uint(arow[0]);
        unsigned a1 = __float_as_uint(arow[8 * MMA_AP]);
        unsigned a2 = __float_as_uint(arow[4]);
        unsigned a3 = __float_as_uint(arow[8 * MMA_AP + 4]);
        const float* b0p = &Bs[(k0 + tg) * MMA_BP + g * 12];
        const float* b1p = &Bs[(k0 + tg + 4) * MMA_BP + g * 12];
        float b0v[8], b1v[8];
        *(float4*)&b0v[0] = *(const float4*)b0p;
        *(float4*)&b0v[4] = *(const float4*)(b0p + 4);
        *(float4*)&b1v[0] = *(const float4*)b1p;
        *(float4*)&b1v[4] = *(const float4*)(b1p + 4);
#pragma unroll
        for (int nt = 0; nt < 8; ++nt) {
            unsigned b0 = __float_as_uint(b0v[nt]);
            unsigned b1 = __float_as_uint(b1v[nt]);
            asm volatile(
                "mma.sync.aligned.m16n8k8.row.col.f32.tf32.tf32.f32 "
                "{%0,%1,%2,%3}, {%4,%5,%6,%7}, {%8,%9}, {%0,%1,%2,%3};"
                : "+f"(c[nt][0]), "+f"(c[nt][1]), "+f"(c[nt][2]), "+f"(c[nt][3])
                : "r"(a0), "r"(a1), "r"(a2), "r"(a3), "r"(b0), "r"(b1));
        }
    }
}

__device__ __forceinline__ void mma_epilogue(int row0, int wp, int g, int tg,
                                             float c[8][4], int n) {
    int r0 = row0 + wp * 16 + g;
#pragma unroll
    for (int nt = 0; nt < 8; ++nt) {
        int col = nt * 8 + 2 * tg;
        if (r0 < n) {
            __half2 h = __floats2half2_rn(c[nt][0], c[nt][1]);
            *(unsigned*)&g_t[(size_t)r0 * 64 + col] = *(unsigned*)&h;
        }
        if (r0 + 8 < n) {
            __half2 h = __floats2half2_rn(c[nt][2], c[nt][3]);
            *(unsigned*)&g_t[(size_t)(r0 + 8) * 64 + col] = *(unsigned*)&h;
        }
    }
}

// ---------------- layer-1 GEMM on tensor cores: g_t = x[n,128] @ W_in[128,64]
// tf32 m16n8k8; x and W_in are rna-rounded ONCE during smem staging.
__global__ __launch_bounds__(256) void k_mma1(const float* __restrict__ A,
                                              const float* __restrict__ W, int n) {
    __shared__ __align__(16) float As[128 * MMA_AP];   // 18.4 KB
    __shared__ __align__(16) float Bs[32 * MMA_BP];    // 13.3 KB

    int tid = threadIdx.x;
    int lane = tid & 31, wp = tid >> 5;
    int row0 = blockIdx.x * 128;
    int g = lane >> 2, tg = lane & 3;

    float c[8][4];
#pragma unroll
    for (int i = 0; i < 8; i++)
#pragma unroll
        for (int j = 0; j < 4; j++) c[i][j] = 0.f;

    for (int kc = 0; kc < 128; kc += 32) {
        __syncthreads();
        // A chunk 128x32 (x, row stride 128), rna -> tf32 at staging
#pragma unroll
        for (int it = 0; it < 4; ++it) {
            int i = tid + it * 256;
            int row = i >> 3, k4 = (i & 7) * 4;
            int gr = row0 + row;
            float4 v = make_float4(0.f, 0.f, 0.f, 0.f);
            if (gr < n) v = *(const float4*)&A[(size_t)gr * 128 + kc + k4];
            v.x = rna_tf32(v.x); v.y = rna_tf32(v.y);
            v.z = rna_tf32(v.z); v.w = rna_tf32(v.w);
            *(float4*)&As[row * MMA_AP + k4] = v;
        }
        // B chunk 32x64 (W_in) -> fragment-major layout, rna at staging
#pragma unroll
        for (int it = 0; it < 2; ++it) {
            int i = tid + it * 256;
            int row = i >> 4, c4 = (i & 15) * 4;
            float4 v = *(const float4*)&W[(size_t)(kc + row) * 64 + c4];
            float vv[4] = { rna_tf32(v.x), rna_tf32(v.y),
                            rna_tf32(v.z), rna_tf32(v.w) };
#pragma unroll
            for (int j = 0; j < 4; ++j) {
                int col = c4 + j;
                Bs[row * MMA_BP + (col & 7) * 12 + (col >> 3)] = vv[j];
            }
        }
        __syncthreads();
        mma_chunk(As, Bs, wp, g, tg, c);
    }
    mma_epilogue(row0, wp, g, tg, c, n);
}

// ---------------- tensor-core GEMM: g_t[n,64](fp16) = g_h[n,64] @ Wr[64,64] --
// Inputs pre-rounded (g_h by prop epilogue, Wr by k_roundw). wsel picks the
// weight slice IN DEVICE CODE (g_wr is a __device__ symbol).
__global__ __launch_bounds__(256) void k_mma(int wsel, int n) {
    __shared__ __align__(16) float As[128 * MMA_AP];
    __shared__ __align__(16) float Bs[32 * MMA_BP];

    const float* Wr = g_wr + (size_t)wsel * 4096;

    int tid = threadIdx.x;
    int lane = tid & 31, wp = tid >> 5;
    int row0 = blockIdx.x * 128;
    int g = lane >> 2, tg = lane & 3;

    float c[8][4];
#pragma unroll
    for (int i = 0; i < 8; i++)
#pragma unroll
        for (int j = 0; j < 4; j++) c[i][j] = 0.f;

    for (int kc = 0; kc < 64; kc += 32) {
        __syncthreads();
#pragma unroll
        for (int it = 0; it < 4; ++it) {
            int i = tid + it * 256;
            int row = i >> 3, k4 = (i & 7) * 4;
            int gr = row0 + row;
            float4 v = make_float4(0.f, 0.f, 0.f, 0.f);
            if (gr < n) v = *(const float4*)&g_h[(size_t)gr * 64 + kc + k4];
            *(float4*)&As[row * MMA_AP + k4] = v;
        }
#pragma unroll
        for (int it = 0; it < 2; ++it) {
            int i = tid + it * 256;
            int row = i >> 4, c4 = (i & 15) * 4;
            float4 v = *(const float4*)&Wr[(size_t)(kc + row) * 64 + c4];
            float vv[4] = { v.x, v.y, v.z, v.w };
#pragma unroll
            for (int j = 0; j < 4; ++j) {
                int col = c4 + j;
                Bs[row * MMA_BP + (col & 7) * 12 + (col >> 3)] = vv[j];
            }
        }
        __syncthreads();
        mma_chunk(As, Bs, wp, g, tg, c);
    }
    mma_epilogue(row0, wp, g, tg, c, n);
}

// ---------------- propagation (64-thread blocks to kill block-tail waves) ----
// out[d] = sum w_e * t[src_e] + dinv^2 * t[d] (+bias)(+relu); t fp16.
// Warp per node, 2 nodes per block, batch-8 MLP gather, inline shuffle consume.
__global__ __launch_bounds__(64) void k_prop(float* __restrict__ outp,
                                             const float* __restrict__ bias, int relu,
                                             int n) {
    float* out = outp ? outp : g_h;
    const __half2* t2 = (const __half2*)g_t;
    int node = (blockIdx.x * 64 + threadIdx.x) >> 5;
    int lane = threadIdx.x & 31;
    if (node >= n) return;
    int beg = foff(node), end = foff(node + 1);
    const __half2* tf = t2 + lane;

    float ax0 = 0.f, ay0 = 0.f, ax1 = 0.f, ay1 = 0.f;
    for (int j = beg; j < end; j += 32) {
        int m = end - j;
        if (m > 32) m = 32;
        int sv = 0;
        float wv = 0.f;
        if (lane < m) {
            int2 mw = g_meta[j + lane];
            sv = mw.x;
            wv = __int_as_float(mw.y);
        }
        int nb8 = (m + 7) >> 3;
        for (int b = 0; b < nb8; ++b) {
            int bb = b * 8;
            float w[8];
            __half2 v[8];
#pragma unroll
            for (int i = 0; i < 8; i++) {
                int s_ = __shfl_sync(0xffffffffu, sv, bb + i);
                w[i] = __shfl_sync(0xffffffffu, wv, bb + i);
                v[i] = tf[(size_t)s_ * 32];
            }
#pragma unroll
            for (int i = 0; i < 8; i++) {
                float2 f = __half22float2(v[i]);
                if (i & 1) { ax1 = fmaf(w[i], f.x, ax1); ay1 = fmaf(w[i], f.y, ay1); }
                else       { ax0 = fmaf(w[i], f.x, ax0); ay0 = fmaf(w[i], f.y, ay0); }
            }
        }
    }
    float accx = ax0 + ax1, accy = ay0 + ay1;
    float dv = g_dinv[node];
    float2 v0 = __half22float2(tf[(size_t)node * 32]);
    float w0 = dv * dv;
    accx = fmaf(w0, v0.x, accx);
    accy = fmaf(w0, v0.y, accy);
    if (bias) { accx += bias[2 * lane]; accy += bias[2 * lane + 1]; }
    if (relu) { accx = fmaxf(accx, 0.f); accy = fmaxf(accy, 0.f); }
    if (!outp) {
        accx = rna_tf32(accx);   // g_h feeds tensor-core GEMM: round here
        accy = rna_tf32(accy);
    }
    *(float2*)(out + (size_t)node * 64 + 2 * lane) = make_float2(accx, accy);
}

// ---------------- launch ----------------
extern "C" void kernel_launch(void* const* d_in, const int* in_sizes, int n_in,
                              void* d_out, int out_size) {
    const float* x     = (const float*)d_in[0];
    const int*   ei    = (const int*)d_in[1];     // int32 (JAX x64 disabled)
    const float* W_in  = (const float*)d_in[2];
    const float* b_in  = (const float*)d_in[3];
    const float* W_h   = (const float*)d_in[4];
    const float* b_h   = (const float*)d_in[5];
    const float* W_out = (const float*)d_in[6];

    int n = in_sizes[0] / 128;
    int E = in_sizes[1] / 2;

    int nb1 = (n + 1023) / 1024;
    int gb = (n + 127) / 128;
    int pb = (n + 1) / 2;        // 64-thread prop blocks, 2 nodes each

    // Fork: CSR build + weight rounding on side stream.
    cudaEventRecord(g_evA, 0);
    cudaStreamWaitEvent(g_s2, g_evA, 0);
    k_count  <<<(E + 255) / 256, 256, 0, g_s2>>>(ei, E);     // slot 1
    k_scan1f <<<nb1, 256, 0, g_s2>>>(n, nb1);                // slot 2
    k_scatter<<<(E + 255) / 256, 256, 0, g_s2>>>(ei, E);     // slot 3

    // layer-1 GEMM on tensor cores, overlaps CSR — slot 4 (ncu target)
    k_mma1<<<gb, 256>>>(x, W_in, n);

    k_roundw <<<64, 256, 0, g_s2>>>(W_h, W_out);
    cudaEventRecord(g_evB, g_s2);                            // CSR + roundw done
    k_reset  <<<(n + 255) / 256, 256, 0, g_s2>>>(n);         // hidden tail work
    cudaEventRecord(g_evC, g_s2);

    // Join: prop needs CSR; subsequent mma needs roundw (covered by evB)
    cudaStreamWaitEvent(0, g_evB, 0);
    k_prop<<<pb, 64>>>(nullptr, b_in, 0, n);                 // prop1 -> g_h (tf32)

    k_mma<<<gb, 256>>>(0, n);                                // gemm(Wh0) -> t
    k_prop<<<pb, 64>>>(nullptr, b_h, 1, n);                  // prop2
    k_mma<<<gb, 256>>>(1, n);                                // gemm(Wh1)
    k_prop<<<pb, 64>>>(nullptr, b_h + 64, 1, n);             // prop3
    k_mma<<<gb, 256>>>(2, n);                                // gemm(Wh2)
    k_prop<<<pb, 64>>>(nullptr, b_h + 128, 1, n);            // prop4
    k_mma<<<gb, 256>>>(3, n);                                // gemm(Wout)
    k_prop<<<pb, 64>>>((float*)d_out, nullptr, 0, n);        // prop5 -> out

    // join side stream (k_reset) so capture sees no unjoined work
    cudaStreamWaitEvent(0, g_evC, 0);
}